// round 8
// baseline (speedup 1.0000x reference)
#include <cuda_runtime.h>
#include <cuda_bf16.h>

typedef unsigned long long u64;

// Problem constants
#define B_   16
#define K_   256
#define T_   64
#define D_   128
// e = C_LIN*(P+Q) + C_ABS*sum_d a_d*|u+vb| + bias   (alpha = 0.2)
#define C_LIN 0.6f
#define C_ABS 0.4f
#define ABSMASK2 0x7FFFFFFF7FFFFFFFULL

__device__ __forceinline__ u64 addx2(u64 a, u64 b) {
    u64 r; asm("add.rn.f32x2 %0,%1,%2;" : "=l"(r) : "l"(a), "l"(b)); return r;
}
__device__ __forceinline__ u64 fmax2p(u64 a, u64 b, u64 c) {
    u64 r; asm("fma.rn.f32x2 %0,%1,%2,%3;" : "=l"(r) : "l"(a), "l"(b), "l"(c)); return r;
}
__device__ __forceinline__ u64 dup2(float v) {
    u64 r; asm("mov.b64 %0, {%1, %1};" : "=l"(r) : "f"(v)); return r;
}
__device__ __forceinline__ float lo32(u64 v) { return __uint_as_float((unsigned)v); }
__device__ __forceinline__ float hi32(u64 v) { return __uint_as_float((unsigned)(v >> 32)); }

// Scratch (device globals: allocation-free rule)
__device__ float g_U [B_*K_*D_];   // u[b,k,d]
__device__ float g_Vb[B_*K_*D_];   // v[b,k,d] + b_lin[d]
__device__ float g_P [B_*K_];      // sum_d a_d * u
__device__ float g_Q [B_*K_];      // sum_d a_d * vb

// ---------------------------------------------------------------------------
// Kernel A: register-tiled GEMM (f32x2) + in-register P/Q reductions.
// 512 threads (16 warps -> 4/SMSP); warp w owns rows 2w, 2w+1; 8 col-groups.
// ---------------------------------------------------------------------------
#define PADA 68
#define KA_SMEM_FLOATS (256*PADA + 32*PADA + 128)

__global__ void __launch_bounds__(512)
kA(const float* __restrict__ x, const float* __restrict__ W,
   const float* __restrict__ b_lin, const float* __restrict__ a)
{
    extern __shared__ float sm[];
    float* Ws  = sm;               // 256 x 68
    float* xs  = sm + 256*PADA;    // 32 x 68
    float* asA = xs + 32*PADA;     // 128

    const int tid  = threadIdx.x;
    const int row0 = blockIdx.x * 32;

    for (int idx = tid; idx < 256*64; idx += 512) {
        const int n = idx >> 6, t = idx & 63;
        Ws[n*PADA + t] = (n < 128) ? W[n*128 + t] : W[(n-128)*128 + 64 + t];
    }
    for (int idx = tid; idx < 32*64; idx += 512) {
        const int r = idx >> 6, t = idx & 63;
        xs[r*PADA + t] = x[(row0 + r)*T_ + t];
    }
    if (tid < 128) asA[tid] = a[tid];
    __syncthreads();

    const int l = tid & 31;
    const int w = tid >> 5;            // 0..15

    u64 acc2[2][8];
    #pragma unroll
    for (int r = 0; r < 2; r++)
        #pragma unroll
        for (int nn = 0; nn < 8; nn++) acc2[r][nn] = 0ull;

    #pragma unroll 4
    for (int k4 = 0; k4 < 16; k4++) {
        ulonglong2 xv[2], wv[8];
        #pragma unroll
        for (int r = 0; r < 2; r++)
            xv[r] = *(const ulonglong2*)(xs + (2*w + r)*PADA + 4*k4);
        #pragma unroll
        for (int nn = 0; nn < 8; nn++)
            wv[nn] = *(const ulonglong2*)(Ws + (l + 32*nn)*PADA + 4*k4);
        #pragma unroll
        for (int r = 0; r < 2; r++)
            #pragma unroll
            for (int nn = 0; nn < 8; nn++) {
                acc2[r][nn] = fmax2p(xv[r].x, wv[nn].x, acc2[r][nn]);
                acc2[r][nn] = fmax2p(xv[r].y, wv[nn].y, acc2[r][nn]);
            }
    }

    float bl[4], av[4];
    #pragma unroll
    for (int nn = 0; nn < 4; nn++) {
        bl[nn] = __ldg(b_lin + l + 32*nn);
        av[nn] = asA[l + 32*nn];
    }

    #pragma unroll
    for (int r = 0; r < 2; r++) {
        const int row = row0 + 2*w + r;
        float uval[4], vval[4];
        #pragma unroll
        for (int nn = 0; nn < 4; nn++) {
            uval[nn] = lo32(acc2[r][nn])   + hi32(acc2[r][nn]);
            vval[nn] = lo32(acc2[r][nn+4]) + hi32(acc2[r][nn+4]) + bl[nn];
            g_U [row*D_ + l + 32*nn] = uval[nn];
            g_Vb[row*D_ + l + 32*nn] = vval[nn];
        }
        float pa = 0.f, qa = 0.f;
        #pragma unroll
        for (int nn = 0; nn < 4; nn++) {
            pa = fmaf(av[nn], uval[nn], pa);
            qa = fmaf(av[nn], vval[nn], qa);
        }
        #pragma unroll
        for (int off = 16; off; off >>= 1) {
            pa += __shfl_down_sync(0xffffffffu, pa, off);
            qa += __shfl_down_sync(0xffffffffu, qa, off);
        }
        if (l == 0) { g_P[row] = pa; g_Q[row] = qa; }
    }
}

// ---------------------------------------------------------------------------
// Kernel B: transposed e-loop (32 warps, dc unrolled x2), split epilogue,
// x-overlay merged into the softmax phase.  Grid (8,16) x 1024 threads.
// ---------------------------------------------------------------------------
#define VBS_F   (K_*132)                   // 33792
#define US_OFF  (VBS_F)                    // 33792
#define AS_OFF  (US_OFF + 32*132)          // 38016
#define QS_OFF  (AS_OFF + 128)             // 38144
#define PS_OFF  (QS_OFF + 256)             // 38400
#define MR_OFF  (PS_OFF + 32)              // 38432
#define SR_OFF  (MR_OFF + 1024)            // 39456
#define WS_OFF  (SR_OFF + 1024)            // 40480
#define KB_SMEM_FLOATS (WS_OFF + K_*36)    // 49696 floats = 198784 B
// overlays inside the dead Vbs region (post e-loop):
#define HR_OFF  16384                      // hred: 32i*4c*33 u64 = 8448 floats

__global__ void __launch_bounds__(1024)
kB(const float* __restrict__ x, const float* __restrict__ a,
   const float* __restrict__ bias, float* __restrict__ out)
{
    extern __shared__ float sm[];
    float* Vbs  = sm;
    float* Us   = sm + US_OFF;
    float* as_  = sm + AS_OFF;
    float* Qs   = sm + QS_OFF;
    float* Ps   = sm + PS_OFF;
    float* mred = sm + MR_OFF;
    float* sred = sm + SR_OFF;
    float* ws   = sm + WS_OFF;   // ws[j*36 + il]

    const int tid = threadIdx.x;
    const int b   = blockIdx.y;
    const int igbase = blockIdx.x * 32;

    // ---- stage Vb[b], 32 U rows, a, Q, P ----
    {
        const float4* vg4  = (const float4*)g_Vb + b * (K_*D_/4);
        float4*       vbs4 = (float4*)Vbs;
        for (int idx = tid; idx < K_*D_/4; idx += 1024) {
            const int j = idx >> 5, c = idx & 31;
            vbs4[j*33 + c] = vg4[idx];
        }
        const float4* ug4 = (const float4*)g_U + (b*K_ + igbase) * (D_/4);
        float4*       us4 = (float4*)Us;
        for (int idx = tid; idx < 32*D_/4; idx += 1024) {
            const int il = idx >> 5, c = idx & 31;
            us4[il*33 + c] = ug4[idx];
        }
        if (tid < 128) as_[tid] = a[tid];
        else if (tid >= 256 && tid < 512) Qs[tid - 256] = g_Q[b*K_ + tid - 256];
        else if (tid >= 512 && tid < 544) Ps[tid - 512] = g_P[b*K_ + igbase + tid - 512];
    }

    const int w  = tid >> 5;
    const int l  = tid & 31;           // lane = local i row
    const int j0 = w * 8;              // warp's j chunk (8 rows)

    // bias prefetch (latency hidden under barrier + e-loop)
    const float4* brow4 = (const float4*)(bias + (igbase + l)*K_ + j0);
    const float4 bv0 = __ldg(brow4);
    const float4 bv1 = __ldg(brow4 + 1);

    __syncthreads();   // B1

    // ---- e-loop (dc unrolled x2): acc[jj] = sum_d a_d*|u_{l,d}+vb_{jj,d}| --
    u64 acc[8];
    #pragma unroll
    for (int jj = 0; jj < 8; jj++) acc[jj] = 0ull;

    {
        const ulonglong2* vbs2 = (const ulonglong2*)Vbs;   // row stride 33
        const ulonglong2* us2  = (const ulonglong2*)Us;
        const ulonglong2* a2   = (const ulonglong2*)as_;
        for (int dc = 0; dc < 32; dc += 2) {
            const ulonglong2 uv0 = us2[l*33 + dc];
            const ulonglong2 uv1 = us2[l*33 + dc + 1];
            const ulonglong2 av0 = a2[dc];
            const ulonglong2 av1 = a2[dc + 1];
            #pragma unroll
            for (int jj = 0; jj < 8; jj++) {
                const ulonglong2 vv0 = vbs2[(j0 + jj)*33 + dc];
                const ulonglong2 vv1 = vbs2[(j0 + jj)*33 + dc + 1];
                u64 z;
                z = addx2(uv0.x, vv0.x); acc[jj] = fmax2p(av0.x, z & ABSMASK2, acc[jj]);
                z = addx2(uv0.y, vv0.y); acc[jj] = fmax2p(av0.y, z & ABSMASK2, acc[jj]);
                z = addx2(uv1.x, vv1.x); acc[jj] = fmax2p(av1.x, z & ABSMASK2, acc[jj]);
                z = addx2(uv1.y, vv1.y); acc[jj] = fmax2p(av1.y, z & ABSMASK2, acc[jj]);
            }
        }
    }

    // ---- finish e for (i=l, j=j0..j0+8) ----
    float e[8];
    {
        const float P = Ps[l];
        const float bb[8] = {bv0.x, bv0.y, bv0.z, bv0.w, bv1.x, bv1.y, bv1.z, bv1.w};
        float m = -1e30f;
        #pragma unroll
        for (int jj = 0; jj < 8; jj++) {
            const float A  = lo32(acc[jj]) + hi32(acc[jj]);
            const float ev = fmaf(C_LIN, P + Qs[j0 + jj], fmaf(C_ABS, A, bb[jj]));
            e[jj] = ev;
            m = fmaxf(m, ev);
        }
        mred[w*32 + l] = m;
    }
    __syncthreads();   // B2 — Vbs dead from here on

    // ---- combine max, exp, sred; overlap x[b] overlay onto dead Vbs ----
    {
        float M = mred[l];
        #pragma unroll
        for (int wp = 1; wp < 32; wp++) M = fmaxf(M, mred[wp*32 + l]);
        float s = 0.f;
        #pragma unroll
        for (int jj = 0; jj < 8; jj++) { e[jj] = __expf(e[jj] - M); s += e[jj]; }
        sred[w*32 + l] = s;
        // x overlay (16 float4 per thread), independent of softmax math
        float4*       xs4 = (float4*)sm;
        const float4* xg4 = (const float4*)x + b * (K_*T_/4);
        for (int idx = tid; idx < K_*T_/4; idx += 1024) xs4[idx] = xg4[idx];
    }
    __syncthreads();   // B3

    {
        float S = sred[l];
        #pragma unroll
        for (int wp = 1; wp < 32; wp++) S += sred[wp*32 + l];
        const float inv = __fdividef(1.f, S);
        #pragma unroll
        for (int jj = 0; jj < 8; jj++)
            ws[(j0 + jj)*36 + l] = e[jj] * inv;
    }
    __syncthreads();   // B4

    // ---- epilogue stage 1: warp = (4 i's, 64 j's); partials -> hred ----
    u64* hred = (u64*)(sm + HR_OFF);   // hred[(i*4 + c)*33 + l]
    {
        const int g  = w & 7;          // i-group: i = 4g..4g+3
        const int c  = w >> 3;         // j-chunk: [64c, 64c+64)
        const u64* xs2 = (const u64*)sm;
        u64 h[4] = {0ull, 0ull, 0ull, 0ull};
        const int jbeg = 64*c;
        #pragma unroll 8
        for (int j = jbeg; j < jbeg + 64; j++) {
            const u64    xv = xs2[j*32 + l];
            const float4 wq = *(const float4*)(ws + j*36 + 4*g);   // broadcast
            h[0] = fmax2p(dup2(wq.x), xv, h[0]);
            h[1] = fmax2p(dup2(wq.y), xv, h[1]);
            h[2] = fmax2p(dup2(wq.z), xv, h[2]);
            h[3] = fmax2p(dup2(wq.w), xv, h[3]);
        }
        #pragma unroll
        for (int ii = 0; ii < 4; ii++)
            hred[((4*g + ii)*4 + c)*33 + l] = h[ii];
    }
    __syncthreads();   // B5

    // ---- epilogue stage 2: warp w -> i row w; combine 4 partials ----
    {
        u64 h = hred[(w*4 + 0)*33 + l];
        h = addx2(h, hred[(w*4 + 1)*33 + l]);
        h = addx2(h, hred[(w*4 + 2)*33 + l]);
        h = addx2(h, hred[(w*4 + 3)*33 + l]);
        const int row = (b*K_ + igbase + w)*T_ + 2*l;
        float2 o;
        o.x = __fdividef(1.f, 1.f + __expf(-lo32(h)));
        o.y = __fdividef(1.f, 1.f + __expf(-hi32(h)));
        *(float2*)(out + row) = o;
    }
}

// ---------------------------------------------------------------------------
extern "C" void kernel_launch(void* const* d_in, const int* in_sizes, int n_in,
                              void* d_out, int out_size)
{
    const float* x     = (const float*)d_in[0];
    // d_in[1] = embedding (unused by the reference computation)
    const float* W     = (const float*)d_in[2];
    const float* b_lin = (const float*)d_in[3];
    const float* a     = (const float*)d_in[4];
    const float* bias  = (const float*)d_in[5];
    float* out = (float*)d_out;

    const int smemA = KA_SMEM_FLOATS * 4;   // 78848 B
    const int smemB = KB_SMEM_FLOATS * 4;   // 198784 B
    cudaFuncSetAttribute(kA, cudaFuncAttributeMaxDynamicSharedMemorySize, smemA);
    cudaFuncSetAttribute(kB, cudaFuncAttributeMaxDynamicSharedMemorySize, smemB);

    kA<<<128, 512, smemA>>>(x, W, b_lin, a);
    kB<<<dim3(8, 16), 1024, smemB>>>(x, a, bias, out);
}